// round 15
// baseline (speedup 1.0000x reference)
#include <cuda_runtime.h>

#define TX 32            // output tile width
#define TY 64            // output tile height
#define RAD 5
#define LTX 42           // TX + 2*RAD
#define LTY 74           // TY + 2*RAD
#define IP 43            // sPQ pitch (u64 units); conflict-free h-window reads
#define HP 33            // h-buffer pitch (u64 units); odd -> conflict-free v reads
#define IMG 512
#define NT 512
#define HTASKS (LTY * 8) // 592 horizontal tasks

typedef unsigned long long u64;

__device__ double g_sum;   // zero-initialized; epilogue resets after each use

__device__ __forceinline__ u64 pk2(float x, float y) {
    u64 r; asm("mov.b64 %0,{%1,%2};" : "=l"(r) : "f"(x), "f"(y)); return r;
}
__device__ __forceinline__ void upk2(u64 v, float& x, float& y) {
    asm("mov.b64 {%0,%1},%2;" : "=f"(x), "=f"(y) : "l"(v));
}
__device__ __forceinline__ u64 fma2(u64 a, u64 b, u64 c) {
    u64 d; asm("fma.rn.f32x2 %0,%1,%2,%3;" : "=l"(d) : "l"(a), "l"(b), "l"(c)); return d;
}
__device__ __forceinline__ u64 mul2(u64 a, u64 b) {
    u64 d; asm("mul.rn.f32x2 %0,%1,%2;" : "=l"(d) : "l"(a), "l"(b)); return d;
}

// dynamic smem layout (u64 units):
//   sPQ : [LTY * IP]   packed (p,q) = (x+y, x-y)      25.5 KB
//   hPQ : [LTY * HP]   conv_h(p,q)                    19.5 KB
//   hSD : [LTY * HP]   conv_h(p^2,q^2)                19.5 KB
#define SMEM_U64 (LTY * IP + 2 * LTY * HP)

__global__ __launch_bounds__(NT, 3) void ssim_kernel(
        const float* __restrict__ A, const float* __restrict__ B) {
    // Gaussian(sigma=1.5, 11 taps), normalized; symmetric -> 6 unique packed weights
    constexpr float WGT[11] = {
        0.00102836f, 0.00759876f, 0.03600077f, 0.10936070f, 0.21300554f,
        0.26601172f,
        0.21300554f, 0.10936070f, 0.03600077f, 0.00759876f, 0.00102836f };

    extern __shared__ u64 dynsm[];
    u64* sPQ = dynsm;
    u64* hPQ = dynsm + LTY * IP;
    u64* hSD = dynsm + LTY * IP + LTY * HP;
    __shared__ float wsum[NT / 32];

    const int tid = threadIdx.x;
    const int tx  = tid & 31;
    const int wid = tid >> 5;          // 0..15
    const int x0 = blockIdx.x * TX - RAD;
    const int y0 = blockIdx.y * TY - RAD;
    const size_t planeOff = (size_t)blockIdx.z * (IMG * IMG);
    const float* __restrict__ pa = A + planeOff;
    const float* __restrict__ pb = B + planeOff;

    // ---- load halo tile: 74 rows over 16 warps (interior fast path) ----
    const bool interior = (x0 >= 0) & (y0 >= 0) &
                          (x0 + LTX <= IMG) & (y0 + LTY <= IMG);
    if (interior) {
        #pragma unroll
        for (int rr = 0; rr < 5; rr++) {
            int r = wid + rr * 16;
            if (rr < 4 || r < LTY) {
                const float* rowa = pa + (y0 + r) * IMG + x0;
                const float* rowb = pb + (y0 + r) * IMG + x0;
                float va = rowa[tx], vb = rowb[tx];
                sPQ[r * IP + tx] = pk2(va + vb, va - vb);
                if (tx < LTX - 32) {
                    float wa = rowa[tx + 32], wb = rowb[tx + 32];
                    sPQ[r * IP + tx + 32] = pk2(wa + wb, wa - wb);
                }
            }
        }
    } else {
        #pragma unroll
        for (int rr = 0; rr < 5; rr++) {
            int r = wid + rr * 16;
            if (rr < 4 || r < LTY) {
                int gy = y0 + r;
                bool rowok = (unsigned)gy < IMG;
                const float* rowa = pa + gy * IMG;
                const float* rowb = pb + gy * IMG;
                int gx = x0 + tx;
                float va = 0.f, vb = 0.f;
                if (rowok && (unsigned)gx < IMG) { va = rowa[gx]; vb = rowb[gx]; }
                sPQ[r * IP + tx] = pk2(va + vb, va - vb);
                if (tx < LTX - 32) {
                    int gx2 = gx + 32;
                    float wa = 0.f, wb = 0.f;
                    if (rowok && (unsigned)gx2 < IMG) { wa = rowa[gx2]; wb = rowb[gx2]; }
                    sPQ[r * IP + tx + 32] = pk2(wa + wb, wa - wb);
                }
            }
        }
    }
    __syncthreads();

    // ---- horizontal pass: static tasks tid and (tid+512 if tid < HTASKS-512) ----
    {
        int g = tid;
        #pragma unroll
        for (int pass = 0; pass < 2; pass++) {
            if (pass == 0 || tid < (HTASKS - NT)) {
                int r  = g >> 3;
                int c0 = (g & 7) * 4;
                const u64* rw = &sPQ[r * IP + c0];
                u64 m[4] = {0,0,0,0};   // conv_h(p,q)
                u64 s[4] = {0,0,0,0};   // conv_h(p^2,q^2)
                #pragma unroll
                for (int k = 0; k < 14; k++) {
                    u64 v  = rw[k];
                    u64 vv = mul2(v, v);
                    #pragma unroll
                    for (int u = 0; u < 4; u++) {
                        int t = k - u;
                        if (t >= 0 && t < 11) {
                            u64 w = pk2(WGT[t], WGT[t]);
                            m[u] = fma2(w, v,  m[u]);
                            s[u] = fma2(w, vv, s[u]);
                        }
                    }
                }
                #pragma unroll
                for (int u = 0; u < 4; u++) {
                    hPQ[r * HP + c0 + u] = m[u];
                    hSD[r * HP + c0 + u] = s[u];
                }
            }
            g = tid + NT;
        }
    }
    __syncthreads();

    // ---- vertical pass + SSIM: one column/thread, 4 consecutive rows (64 rows total) ----
    const int r0 = wid * 4;
    u64 M[4] = {0,0,0,0};
    u64 S[4] = {0,0,0,0};
    #pragma unroll
    for (int k = 0; k < 14; k++) {
        int row = r0 + k;
        u64 a = hPQ[row * HP + tx];
        u64 b = hSD[row * HP + tx];
        #pragma unroll
        for (int u = 0; u < 4; u++) {
            int t = k - u;
            if (t >= 0 && t < 11) {
                u64 w = pk2(WGT[t], WGT[t]);
                M[u] = fma2(w, a, M[u]);
                S[u] = fma2(w, b, S[u]);
            }
        }
    }

    float acc = 0.f;
    const float C1 = 1e-4f;   // 0.01^2
    const float C2 = 9e-4f;   // 0.03^2
    #pragma unroll
    for (int u = 0; u < 4; u++) {
        float Mp, Mq, Sp, Sq;
        upk2(M[u], Mp, Mq);
        upk2(S[u], Sp, Sq);
        float Mp2 = Mp * Mp, Mq2 = Mq * Mq;
        float Ep = Sp - Mp2;       // conv(p^2) - Mp^2
        float Eq = Sq - Mq2;
        // mu12 = (Mp2-Mq2)/4 ; mu1^2+mu2^2 = (Mp2+Mq2)/2
        // sig12 = (Ep-Eq)/4  ; sig1^2+sig2^2 = (Ep+Eq)/2
        float num = (0.5f * (Mp2 - Mq2) + C1) * (0.5f * (Ep - Eq) + C2);
        float den = (0.5f * (Mp2 + Mq2) + C1) * (0.5f * (Ep + Eq) + C2);
        acc += __fdividef(num, den);
    }

    // ---- block reduction -> one double red.add per block (overlapped, no fence) ----
    #pragma unroll
    for (int o = 16; o > 0; o >>= 1)
        acc += __shfl_xor_sync(0xffffffffu, acc, o);
    if (tx == 0) wsum[wid] = acc;
    __syncthreads();
    if (tid == 0) {
        float t = 0.f;
        #pragma unroll
        for (int wi = 0; wi < NT / 32; wi++) t += wsum[wi];
        atomicAdd(&g_sum, (double)t);
    }
}

__global__ void final_kernel(float* out, double inv_n) {
    out[0] = (float)(1.0 - g_sum * inv_n);
    g_sum = 0.0;   // reset for the next replay (same-stream ordering keeps this deterministic)
}

extern "C" void kernel_launch(void* const* d_in, const int* in_sizes, int n_in,
                              void* d_out, int out_size) {
    const float* A = (const float*)d_in[0];   // clean
    const float* B = (const float*)d_in[1];   // adversarial
    float* out = (float*)d_out;
    long long total = (long long)in_sizes[0];
    int planes = (int)(total / (IMG * IMG));  // 96 = 32*3

    const int smemBytes = SMEM_U64 * (int)sizeof(u64);   // ~64.9 KB
    cudaFuncSetAttribute(ssim_kernel,
                         cudaFuncAttributeMaxDynamicSharedMemorySize, smemBytes);

    dim3 grid(IMG / TX, IMG / TY, planes);
    ssim_kernel<<<grid, NT, smemBytes>>>(A, B);
    final_kernel<<<1, 1>>>(out, 1.0 / (double)total);
}